// round 7
// baseline (speedup 1.0000x reference)
#include <cuda_runtime.h>
#include <math.h>

// ---------------------------------------------------------------------------
// EMG_SyEMB fused kernel, sm_103a. R7: vectorized phase-2/4 windows (quad-j),
// register-side |x|, pre-duplicated xs for MOV-free f32x2 GEMM.
// One block = (batch b, 40-patch tile = 1000 timesteps).
// ---------------------------------------------------------------------------

namespace {
constexpr int B_ = 64, T_ = 50000, C_ = 4, D_ = 160, P_ = 25, L_ = 2000;
constexpr int TILE   = 1000;
constexpr int NPATCH = TILE / P_;      // 40
constexpr int HALO   = 16;
constexpr int XLEN   = TILE + 2*HALO;  // 1032
constexpr int S0LEN  = TILE + 8;       // 1008
constexpr int NTH    = 512;
constexpr int TPB    = L_ / NPATCH;    // 50
constexpr int WPADW  = 164;            // WS row stride (d), %4==0 for float4
constexpr int P2PAD  = 84;             // XS2 row stride (2p duplicated), %2==0

constexpr int OFF_SX   = 0;                      // [4][1032]
constexpr int OFF_ADX  = OFF_SX  + 4*XLEN;       // [4][1032]
constexpr int OFF_S0   = OFF_ADX + 4*XLEN;       // [4][1008]
constexpr int OFF_SM   = OFF_S0  + 4*S0LEN;      // [1000][4]
constexpr int OFF_XS2  = OFF_SM  + TILE*4;       // [100][84]  xs duplicated (v,v)
constexpr int OFF_H    = OFF_XS2 + 100*P2PAD;    // [40][160]
constexpr int OFF_WS   = OFF_H   + NPATCH*D_;    // [100][164]
constexpr int OFF_WENV = OFF_WS  + 100*WPADW;    // [4][25]
constexpr int OFF_WBUR = OFF_WENV + 100;         // [4][9]
constexpr int OFF_WDW  = OFF_WBUR + 36;          // [4][9]
constexpr int OFF_WPW  = OFF_WDW  + 36;          // [4][4]
constexpr int OFF_WN   = OFF_WPW  + 16;          // [4][4]
constexpr int OFF_G    = OFF_WN   + 16;          // [160]
constexpr int OFF_BT   = OFF_G    + D_;          // [160]
constexpr int SMEM_FLOATS = OFF_BT + D_;         // 48012 floats = 192048 B
}

__device__ __forceinline__ float gelu_(float x) {
    return 0.5f * x * (1.0f + erff(x * 0.70710678118654752440f));
}

// packed fp32x2 helpers (sm_103a FFMA2 — only reachable via PTX)
__device__ __forceinline__ void fma2_(unsigned long long& d,
                                      unsigned long long a, unsigned long long b) {
    asm("fma.rn.f32x2 %0, %1, %2, %0;" : "+l"(d) : "l"(a), "l"(b));
}
__device__ __forceinline__ unsigned long long pk2_(float lo, float hi) {
    unsigned long long r;
    asm("mov.b64 %0, {%1, %2};" : "=l"(r) : "f"(lo), "f"(hi));
    return r;
}
__device__ __forceinline__ float2 upk2_(unsigned long long v) {
    float2 r;
    asm("mov.b64 {%0, %1}, %2;" : "=f"(r.x), "=f"(r.y) : "l"(v));
    return r;
}

__global__ void __launch_bounds__(NTH, 1)
emg_fused_kernel(const float* __restrict__ X,  const float* __restrict__ Mk,
                 const float* __restrict__ w_env, const float* __restrict__ w_bur,
                 const float* __restrict__ syn,   const float* __restrict__ w_dw,
                 const float* __restrict__ w_pw,  const float* __restrict__ w_proj,
                 const float* __restrict__ gam,   const float* __restrict__ bet,
                 float* __restrict__ out_h, float* __restrict__ out_mp)
{
    extern __shared__ float smem[];
    const int tid  = threadIdx.x;
    const int b    = blockIdx.x / TPB;
    const int tile = blockIdx.x % TPB;
    const int t0   = tile * TILE;

    // ---- weights to smem --------------------------------------------------
    for (int i = tid; i < D_ * 100; i += NTH) {
        int d = i / 100, k = i - d * 100;
        smem[OFF_WS + k * WPADW + d] = w_proj[i];
    }
    for (int i = tid; i < 100; i += NTH) smem[OFF_WENV + i] = w_env[i];
    for (int i = tid; i < 36;  i += NTH) smem[OFF_WBUR + i] = w_bur[i];
    for (int i = tid; i < 36;  i += NTH) smem[OFF_WDW  + i] = w_dw[i];
    for (int i = tid; i < 16;  i += NTH) smem[OFF_WPW  + i] = w_pw[i];
    for (int i = tid; i < D_;  i += NTH) { smem[OFF_G + i] = gam[i]; smem[OFF_BT + i] = bet[i]; }
    if (tid == 0) {
        float sp[16];
        for (int m = 0; m < 4; m++) {
            float s = 0.f;
            for (int c = 0; c < 4; c++) {
                float x = syn[m * 4 + c];
                float v = (x > 20.f) ? x : log1pf(expf(x));
                sp[m * 4 + c] = v; s += v;
            }
            float inv = 1.f / fmaxf(s, 1e-6f);
            for (int c = 0; c < 4; c++) smem[OFF_WN + m * 4 + c] = sp[m * 4 + c] * inv;
        }
    }
    __syncthreads();

    // ---- phase 1: x = X*M (halo), Sm = clip(W@(M>0),0,1) ------------------
    const float4* Xb = reinterpret_cast<const float4*>(X)  + (size_t)b * T_;
    const float4* Mb = reinterpret_cast<const float4*>(Mk) + (size_t)b * T_;
    for (int tt = tid; tt < XLEN; tt += NTH) {
        int g = t0 - HALO + tt;
        float x0 = 0.f, x1 = 0.f, x2 = 0.f, x3 = 0.f;
        if ((unsigned)g < (unsigned)T_) {
            float4 xv = Xb[g];
            float4 mv = Mb[g];
            x0 = xv.x * mv.x; x1 = xv.y * mv.y; x2 = xv.z * mv.z; x3 = xv.w * mv.w;
            int u = tt - HALO;
            if ((unsigned)u < (unsigned)TILE) {
                float m0 = mv.x > 0.f ? 1.f : 0.f, m1 = mv.y > 0.f ? 1.f : 0.f;
                float m2 = mv.z > 0.f ? 1.f : 0.f, m3 = mv.w > 0.f ? 1.f : 0.f;
                float4 s;
                s.x = fminf(fmaxf(smem[OFF_WN+ 0]*m0 + smem[OFF_WN+ 1]*m1 + smem[OFF_WN+ 2]*m2 + smem[OFF_WN+ 3]*m3, 0.f), 1.f);
                s.y = fminf(fmaxf(smem[OFF_WN+ 4]*m0 + smem[OFF_WN+ 5]*m1 + smem[OFF_WN+ 6]*m2 + smem[OFF_WN+ 7]*m3, 0.f), 1.f);
                s.z = fminf(fmaxf(smem[OFF_WN+ 8]*m0 + smem[OFF_WN+ 9]*m1 + smem[OFF_WN+10]*m2 + smem[OFF_WN+11]*m3, 0.f), 1.f);
                s.w = fminf(fmaxf(smem[OFF_WN+12]*m0 + smem[OFF_WN+13]*m1 + smem[OFF_WN+14]*m2 + smem[OFF_WN+15]*m3, 0.f), 1.f);
                reinterpret_cast<float4*>(smem + OFF_SM)[u] = s;
            }
        }
        smem[OFF_SX + 0*XLEN + tt] = x0;
        smem[OFF_SX + 1*XLEN + tt] = x1;
        smem[OFF_SX + 2*XLEN + tt] = x2;
        smem[OFF_SX + 3*XLEN + tt] = x3;
    }
    __syncthreads();

    // ---- phase 1b: |dx| only (|x| now computed in registers in phase 2) ---
    for (int i = tid; i < 4 * XLEN; i += NTH) {
        int c = i / XLEN, tt = i - c * XLEN;
        int g = t0 - HALO + tt;
        float v = 0.f;
        if (tt >= 1 && g >= 1 && g < T_)
            v = fabsf(smem[OFF_SX + c*XLEN + tt] - smem[OFF_SX + c*XLEN + tt - 1]);
        smem[OFF_ADX + c*XLEN + tt] = v;
    }
    __syncthreads();

    // ---- phase 2+3: S0 = W @ (.9 env + .6 burst + .2 x), quad-j ----------
    // 252 threads, 4 consecutive j each. Window loads vectorized (LDS.128),
    // |x| via FABS in registers, weights amortized 4x, float4 stores.
    if (tid < 252) {
        const int j0 = tid * 4;
        float s[4][4];                               // [m][j]
        #pragma unroll
        for (int m = 0; m < 4; m++)
            #pragma unroll
            for (int X = 0; X < 4; X++) s[m][X] = 0.f;

        #pragma unroll
        for (int c = 0; c < 4; c++) {
            const float* xc = smem + OFF_SX  + c * XLEN;
            const float* dc = smem + OFF_ADX + c * XLEN;
            // SX window [j0, j0+28): 7 x LDS.128
            float4 xq[7];
            #pragma unroll
            for (int q = 0; q < 7; q++)
                xq[q] = *reinterpret_cast<const float4*>(xc + j0 + q * 4);
            float aw[28];
            #pragma unroll
            for (int q = 0; q < 7; q++) {
                aw[q*4+0] = fabsf(xq[q].x); aw[q*4+1] = fabsf(xq[q].y);
                aw[q*4+2] = fabsf(xq[q].z); aw[q*4+3] = fabsf(xq[q].w);
            }
            // ADX window [j0+8, j0+20): 3 x LDS.128
            float dw[12];
            #pragma unroll
            for (int q = 0; q < 3; q++) {
                float4 t = *reinterpret_cast<const float4*>(dc + j0 + 8 + q * 4);
                dw[q*4+0] = t.x; dw[q*4+1] = t.y; dw[q*4+2] = t.z; dw[q*4+3] = t.w;
            }
            const float* we = smem + OFF_WENV + c * 25;
            float env[4] = {0.f, 0.f, 0.f, 0.f};
            #pragma unroll
            for (int k = 0; k < 25; k++) {
                float w = we[k];
                env[0] = fmaf(aw[k    ], w, env[0]);
                env[1] = fmaf(aw[k + 1], w, env[1]);
                env[2] = fmaf(aw[k + 2], w, env[2]);
                env[3] = fmaf(aw[k + 3], w, env[3]);
            }
            const float* wb = smem + OFF_WBUR + c * 9;
            float bur[4] = {0.f, 0.f, 0.f, 0.f};
            #pragma unroll
            for (int k = 0; k < 9; k++) {
                float w = wb[k];
                bur[0] = fmaf(dw[k    ], w, bur[0]);
                bur[1] = fmaf(dw[k + 1], w, bur[1]);
                bur[2] = fmaf(dw[k + 2], w, bur[2]);
                bur[3] = fmaf(dw[k + 3], w, bur[3]);
            }
            const float wn0 = smem[OFF_WN +  0 + c], wn1 = smem[OFF_WN +  4 + c];
            const float wn2 = smem[OFF_WN +  8 + c], wn3 = smem[OFF_WN + 12 + c];
            const float xcl[4] = {xq[3].x, xq[3].y, xq[3].z, xq[3].w}; // x at j+12
            #pragma unroll
            for (int X = 0; X < 4; X++) {
                float xm = 0.9f * env[X] + 0.6f * bur[X] + 0.2f * xcl[X];
                s[0][X] = fmaf(wn0, xm, s[0][X]);
                s[1][X] = fmaf(wn1, xm, s[1][X]);
                s[2][X] = fmaf(wn2, xm, s[2][X]);
                s[3][X] = fmaf(wn3, xm, s[3][X]);
            }
        }
        // reference zero-pads S outside [0,T)
        #pragma unroll
        for (int X = 0; X < 4; X++) {
            if ((unsigned)(t0 - 4 + j0 + X) >= (unsigned)T_) {
                s[0][X] = s[1][X] = s[2][X] = s[3][X] = 0.f;
            }
        }
        #pragma unroll
        for (int m = 0; m < 4; m++)
            *reinterpret_cast<float4*>(smem + OFF_S0 + m * S0LEN + j0) =
                make_float4(s[m][0], s[m][1], s[m][2], s[m][3]);
    }
    __syncthreads();

    // ---- phase 4: dwK9+gelu, pw4x4+gelu, gate; consecutive dual-u --------
    // 500 threads, u = 2*tid, 2*tid+1. float2 window loads, duplicated stores.
    if (tid < 500) {
        const int uA = 2 * tid, uB = uA + 1;
        float g1A[4], g1B[4];
        #pragma unroll
        for (int m = 0; m < 4; m++) {
            const float* s0 = smem + OFF_S0 + m * S0LEN;
            // window [uA, uA+10): 5 x LDS.64
            float v[10];
            #pragma unroll
            for (int q = 0; q < 5; q++) {
                float2 t = *reinterpret_cast<const float2*>(s0 + uA + q * 2);
                v[q*2] = t.x; v[q*2+1] = t.y;
            }
            const float* wd = smem + OFF_WDW + m * 9;
            float aA = 0.f, aB = 0.f;
            #pragma unroll
            for (int k = 0; k < 9; k++) {
                float w = wd[k];
                aA = fmaf(v[k    ], w, aA);
                aB = fmaf(v[k + 1], w, aB);
            }
            g1A[m] = gelu_(aA);
            g1B[m] = gelu_(aB);
        }
        float4 smA = reinterpret_cast<const float4*>(smem + OFF_SM)[uA];
        float4 smB = reinterpret_cast<const float4*>(smem + OFF_SM)[uB];
        float sArA[4] = {smA.x, smA.y, smA.z, smA.w};
        float sArB[4] = {smB.x, smB.y, smB.z, smB.w};
        const int pA = uA / 25, jjA = uA - pA * 25;
        const int pB = uB / 25, jjB = uB - pB * 25;
        #pragma unroll
        for (int o = 0; o < 4; o++) {
            float w0 = smem[OFF_WPW + o*4 + 0], w1 = smem[OFF_WPW + o*4 + 1];
            float w2 = smem[OFF_WPW + o*4 + 2], w3 = smem[OFF_WPW + o*4 + 3];
            float aA = w0*g1A[0] + w1*g1A[1] + w2*g1A[2] + w3*g1A[3];
            float aB = w0*g1B[0] + w1*g1B[1] + w2*g1B[2] + w3*g1B[3];
            float xA = gelu_(aA) * sArA[o];
            float xB = gelu_(aB) * sArB[o];
            // duplicated store (v,v) -> MOV-free f32x2 GEMM loads
            *reinterpret_cast<float2*>(smem + OFF_XS2 + (o*25 + jjA) * P2PAD + 2*pA) = make_float2(xA, xA);
            *reinterpret_cast<float2*>(smem + OFF_XS2 + (o*25 + jjB) * P2PAD + 2*pB) = make_float2(xB, xB);
        }
    }
    __syncthreads();

    // ---- phase 5: patch GEMM h[p][d] = sum_k xs[k][p]*wT[k][d] -----------
    // 400 threads: 4 consecutive d x 4 p. Per k: 1 LDS.128 + 4 LDS.64 + 8 FFMA2.
    if (tid < 400) {
        const int d0    = (tid % 40) * 4;
        const int pbase = (tid / 40) * 4;
        unsigned long long acc[4][2];                // [p][dpair]
        #pragma unroll
        for (int j = 0; j < 4; j++) { acc[j][0] = 0ull; acc[j][1] = 0ull; }
        const float* ws  = smem + OFF_WS  + d0;
        const float* xs2 = smem + OFF_XS2 + 2 * pbase;
        #pragma unroll 2
        for (int k = 0; k < 100; k++) {
            const float4 w = *reinterpret_cast<const float4*>(ws + k * WPADW);
            unsigned long long w01 = pk2_(w.x, w.y);
            unsigned long long w23 = pk2_(w.z, w.w);
            unsigned long long x0 = *reinterpret_cast<const unsigned long long*>(xs2 + k * P2PAD);
            unsigned long long x1 = *reinterpret_cast<const unsigned long long*>(xs2 + k * P2PAD + 2);
            unsigned long long x2 = *reinterpret_cast<const unsigned long long*>(xs2 + k * P2PAD + 4);
            unsigned long long x3 = *reinterpret_cast<const unsigned long long*>(xs2 + k * P2PAD + 6);
            fma2_(acc[0][0], w01, x0); fma2_(acc[0][1], w23, x0);
            fma2_(acc[1][0], w01, x1); fma2_(acc[1][1], w23, x1);
            fma2_(acc[2][0], w01, x2); fma2_(acc[2][1], w23, x2);
            fma2_(acc[3][0], w01, x3); fma2_(acc[3][1], w23, x3);
        }
        #pragma unroll
        for (int j = 0; j < 4; j++) {
            float2 lo = upk2_(acc[j][0]);
            float2 hi = upk2_(acc[j][1]);
            *reinterpret_cast<float4*>(smem + OFF_H + (pbase + j) * D_ + d0) =
                make_float4(lo.x, lo.y, hi.x, hi.y);
        }
    }
    __syncthreads();

    // ---- phase 6: LayerNorm(D=160) + m_patch -----------------------------
    const int wid = tid >> 5, lane = tid & 31;
    for (int p = wid; p < NPATCH; p += NTH / 32) {
        const float* hp = smem + OFF_H + p * D_;
        float s = 0.f;
        #pragma unroll
        for (int i = 0; i < 5; i++) s += hp[lane + 32 * i];
        #pragma unroll
        for (int o = 16; o; o >>= 1) s += __shfl_xor_sync(0xffffffffu, s, o);
        float mu = s * (1.f / 160.f);
        float v = 0.f;
        #pragma unroll
        for (int i = 0; i < 5; i++) { float d = hp[lane + 32 * i] - mu; v = fmaf(d, d, v); }
        #pragma unroll
        for (int o = 16; o; o >>= 1) v += __shfl_xor_sync(0xffffffffu, v, o);
        float rstd = rsqrtf(v * (1.f / 160.f) + 1e-5f);
        const int pg = tile * NPATCH + p;
        float* oh = out_h + ((size_t)b * L_ + pg) * D_;
        #pragma unroll
        for (int i = 0; i < 5; i++) {
            int d = lane + 32 * i;
            oh[d] = (hp[d] - mu) * rstd * smem[OFF_G + d] + smem[OFF_BT + d];
        }
        int pred = 0;
        if (lane < 25) {
            float4 q = reinterpret_cast<const float4*>(smem + OFF_SM)[p * 25 + lane];
            pred = (q.x + q.y + q.z + q.w) > 0.f ? 1 : 0;
        }
        unsigned bal = __ballot_sync(0xffffffffu, pred);
        if (lane == 0) {
            int cnt = __popc(bal & 0x1ffffffu);
            out_mp[(size_t)b * L_ + pg] = ((float)cnt * (1.f / 25.f) > 0.1f) ? 1.f : 0.f;
        }
    }
}

extern "C" void kernel_launch(void* const* d_in, const int* in_sizes, int n_in,
                              void* d_out, int out_size) {
    const float* X      = (const float*)d_in[0];
    const float* M      = (const float*)d_in[1];
    const float* w_env  = (const float*)d_in[2];
    const float* w_bur  = (const float*)d_in[3];
    const float* syn    = (const float*)d_in[4];
    const float* w_dw   = (const float*)d_in[5];
    const float* w_pw   = (const float*)d_in[6];
    const float* w_proj = (const float*)d_in[7];
    const float* gam    = (const float*)d_in[8];
    const float* bet    = (const float*)d_in[9];

    float* out_h  = (float*)d_out;
    float* out_mp = out_h + (size_t)B_ * L_ * D_;

    cudaFuncSetAttribute(emg_fused_kernel,
                         cudaFuncAttributeMaxDynamicSharedMemorySize,
                         SMEM_FLOATS * (int)sizeof(float));

    emg_fused_kernel<<<B_ * TPB, NTH, SMEM_FLOATS * (int)sizeof(float)>>>(
        X, M, w_env, w_bur, syn, w_dw, w_pw, w_proj, gam, bet, out_h, out_mp);
}

// round 10
// speedup vs baseline: 1.4226x; 1.4226x over previous
#include <cuda_runtime.h>
#include <math.h>

// ---------------------------------------------------------------------------
// EMG_SyEMB fused kernel, sm_103a. R8: R6 skeleton + MOV-free f32x2 GEMM +
// pressure-controlled vectorized phase-2 (dual-j, unroll-1 channel loop).
// One block = (batch b, 40-patch tile = 1000 timesteps).
// ---------------------------------------------------------------------------

namespace {
constexpr int B_ = 64, T_ = 50000, C_ = 4, D_ = 160, P_ = 25, L_ = 2000;
constexpr int TILE   = 1000;
constexpr int NPATCH = TILE / P_;      // 40
constexpr int HALO   = 16;
constexpr int XLEN   = TILE + 2*HALO;  // 1032
constexpr int S0LEN  = TILE + 8;       // 1008
constexpr int NTH    = 512;
constexpr int TPB    = L_ / NPATCH;    // 50
constexpr int WPADW  = 164;            // WS row stride (d), %4==0 for float4
constexpr int P2PAD  = 84;             // XS2 row stride (2p duplicated)

constexpr int OFF_SX   = 0;                      // [4][1032]
constexpr int OFF_ADX  = OFF_SX  + 4*XLEN;       // [4][1032]
constexpr int OFF_S0   = OFF_ADX + 4*XLEN;       // [4][1008]
constexpr int OFF_SM   = OFF_S0  + 4*S0LEN;      // [1000][4]
constexpr int OFF_XS2  = OFF_SM  + TILE*4;       // [100][84] xs duplicated (v,v)
constexpr int OFF_H    = OFF_XS2 + 100*P2PAD;    // [40][160]
constexpr int OFF_WS   = OFF_H   + NPATCH*D_;    // [100][164]
constexpr int OFF_WENV = OFF_WS  + 100*WPADW;    // [4][28] padded
constexpr int OFF_WBUR = OFF_WENV + 112;         // [4][12] padded
constexpr int OFF_WDW  = OFF_WBUR + 48;          // [4][12] padded
constexpr int OFF_WPW  = OFF_WDW  + 48;          // [4][4]
constexpr int OFF_WN   = OFF_WPW  + 16;          // [4][4]
constexpr int OFF_G    = OFF_WN   + 16;          // [160]
constexpr int OFF_BT   = OFF_G    + D_;          // [160]
constexpr int SMEM_FLOATS = OFF_BT + D_;         // 48048 floats = 192192 B
}

__device__ __forceinline__ float gelu_(float x) {
    return 0.5f * x * (1.0f + erff(x * 0.70710678118654752440f));
}

// packed fp32x2 helpers (sm_103a FFMA2 — only reachable via PTX)
__device__ __forceinline__ void fma2_(unsigned long long& d,
                                      unsigned long long a, unsigned long long b) {
    asm("fma.rn.f32x2 %0, %1, %2, %0;" : "+l"(d) : "l"(a), "l"(b));
}
__device__ __forceinline__ float2 upk2_(unsigned long long v) {
    float2 r;
    asm("mov.b64 {%0, %1}, %2;" : "=f"(r.x), "=f"(r.y) : "l"(v));
    return r;
}

__global__ void __launch_bounds__(NTH, 1)
emg_fused_kernel(const float* __restrict__ X,  const float* __restrict__ Mk,
                 const float* __restrict__ w_env, const float* __restrict__ w_bur,
                 const float* __restrict__ syn,   const float* __restrict__ w_dw,
                 const float* __restrict__ w_pw,  const float* __restrict__ w_proj,
                 const float* __restrict__ gam,   const float* __restrict__ bet,
                 float* __restrict__ out_h, float* __restrict__ out_mp)
{
    extern __shared__ float smem[];
    const int tid  = threadIdx.x;
    const int b    = blockIdx.x / TPB;
    const int tile = blockIdx.x % TPB;
    const int t0   = tile * TILE;

    // ---- weights to smem --------------------------------------------------
    for (int i = tid; i < D_ * 100; i += NTH) {
        int d = i / 100, k = i - d * 100;
        smem[OFF_WS + k * WPADW + d] = w_proj[i];
    }
    // padded small-weight rows (pad entries zeroed)
    for (int i = tid; i < 112; i += NTH) {
        int c = i / 28, k = i - c * 28;
        smem[OFF_WENV + i] = (k < 25) ? w_env[c * 25 + k] : 0.f;
    }
    for (int i = tid; i < 48; i += NTH) {
        int c = i / 12, k = i - c * 12;
        smem[OFF_WBUR + i] = (k < 9) ? w_bur[c * 9 + k] : 0.f;
        smem[OFF_WDW  + i] = (k < 9) ? w_dw [c * 9 + k] : 0.f;
    }
    for (int i = tid; i < 16;  i += NTH) smem[OFF_WPW + i] = w_pw[i];
    for (int i = tid; i < D_;  i += NTH) { smem[OFF_G + i] = gam[i]; smem[OFF_BT + i] = bet[i]; }
    if (tid == 0) {
        float sp[16];
        for (int m = 0; m < 4; m++) {
            float s = 0.f;
            for (int c = 0; c < 4; c++) {
                float x = syn[m * 4 + c];
                float v = (x > 20.f) ? x : log1pf(expf(x));
                sp[m * 4 + c] = v; s += v;
            }
            float inv = 1.f / fmaxf(s, 1e-6f);
            for (int c = 0; c < 4; c++) smem[OFF_WN + m * 4 + c] = sp[m * 4 + c] * inv;
        }
    }
    __syncthreads();

    // ---- phase 1: x = X*M (halo), Sm = clip(W@(M>0),0,1) ------------------
    const float4* Xb = reinterpret_cast<const float4*>(X)  + (size_t)b * T_;
    const float4* Mb = reinterpret_cast<const float4*>(Mk) + (size_t)b * T_;
    for (int tt = tid; tt < XLEN; tt += NTH) {
        int g = t0 - HALO + tt;
        float x0 = 0.f, x1 = 0.f, x2 = 0.f, x3 = 0.f;
        if ((unsigned)g < (unsigned)T_) {
            float4 xv = Xb[g];
            float4 mv = Mb[g];
            x0 = xv.x * mv.x; x1 = xv.y * mv.y; x2 = xv.z * mv.z; x3 = xv.w * mv.w;
            int u = tt - HALO;
            if ((unsigned)u < (unsigned)TILE) {
                float m0 = mv.x > 0.f ? 1.f : 0.f, m1 = mv.y > 0.f ? 1.f : 0.f;
                float m2 = mv.z > 0.f ? 1.f : 0.f, m3 = mv.w > 0.f ? 1.f : 0.f;
                float4 s;
                s.x = fminf(fmaxf(smem[OFF_WN+ 0]*m0 + smem[OFF_WN+ 1]*m1 + smem[OFF_WN+ 2]*m2 + smem[OFF_WN+ 3]*m3, 0.f), 1.f);
                s.y = fminf(fmaxf(smem[OFF_WN+ 4]*m0 + smem[OFF_WN+ 5]*m1 + smem[OFF_WN+ 6]*m2 + smem[OFF_WN+ 7]*m3, 0.f), 1.f);
                s.z = fminf(fmaxf(smem[OFF_WN+ 8]*m0 + smem[OFF_WN+ 9]*m1 + smem[OFF_WN+10]*m2 + smem[OFF_WN+11]*m3, 0.f), 1.f);
                s.w = fminf(fmaxf(smem[OFF_WN+12]*m0 + smem[OFF_WN+13]*m1 + smem[OFF_WN+14]*m2 + smem[OFF_WN+15]*m3, 0.f), 1.f);
                reinterpret_cast<float4*>(smem + OFF_SM)[u] = s;
            }
        }
        smem[OFF_SX + 0*XLEN + tt] = x0;
        smem[OFF_SX + 1*XLEN + tt] = x1;
        smem[OFF_SX + 2*XLEN + tt] = x2;
        smem[OFF_SX + 3*XLEN + tt] = x3;
    }
    __syncthreads();

    // ---- phase 1b: |dx| only ---------------------------------------------
    for (int i = tid; i < 4 * XLEN; i += NTH) {
        int c = i / XLEN, tt = i - c * XLEN;
        int g = t0 - HALO + tt;
        float v = 0.f;
        if (tt >= 1 && g >= 1 && g < T_)
            v = fabsf(smem[OFF_SX + c*XLEN + tt] - smem[OFF_SX + c*XLEN + tt - 1]);
        smem[OFF_ADX + c*XLEN + tt] = v;
    }
    __syncthreads();

    // ---- phase 2+3: S0 = W @ (.9 env + .6 burst + .2 x) ------------------
    // 504 threads, 2 consecutive j each (j0 = 2*tid). Vector window loads,
    // |x| via FABS in regs. Channel loop NOT unrolled (register pressure!).
    if (tid < 504) {
        const int j0 = 2 * tid;
        float s00 = 0.f, s01 = 0.f, s10 = 0.f, s11 = 0.f;
        float s20 = 0.f, s21 = 0.f, s30 = 0.f, s31 = 0.f;
        #pragma unroll 1
        for (int c = 0; c < 4; c++) {
            const float* xc = smem + OFF_SX  + c * XLEN;
            // env weights (7 x LDS.128, pads unused) + |x| window (13 x LDS.64)
            float we[28];
            #pragma unroll
            for (int q = 0; q < 7; q++)
                *reinterpret_cast<float4*>(we + 4*q) =
                    *reinterpret_cast<const float4*>(smem + OFF_WENV + c*28 + 4*q);
            float aw[26];
            #pragma unroll
            for (int q = 0; q < 13; q++) {
                float2 t = *reinterpret_cast<const float2*>(xc + j0 + 2*q);
                aw[2*q] = fabsf(t.x); aw[2*q+1] = fabsf(t.y);
            }
            float env0 = 0.f, env1 = 0.f;
            #pragma unroll
            for (int k = 0; k < 25; k++) {
                env0 = fmaf(aw[k    ], we[k], env0);
                env1 = fmaf(aw[k + 1], we[k], env1);
            }
            // burst weights (3 x LDS.128) + |dx| window (5 x LDS.64)
            float wb[12];
            #pragma unroll
            for (int q = 0; q < 3; q++)
                *reinterpret_cast<float4*>(wb + 4*q) =
                    *reinterpret_cast<const float4*>(smem + OFF_WBUR + c*12 + 4*q);
            float dw[10];
            #pragma unroll
            for (int q = 0; q < 5; q++) {
                float2 t = *reinterpret_cast<const float2*>(smem + OFF_ADX + c*XLEN + j0 + 8 + 2*q);
                dw[2*q] = t.x; dw[2*q+1] = t.y;
            }
            float bur0 = 0.f, bur1 = 0.f;
            #pragma unroll
            for (int k = 0; k < 9; k++) {
                bur0 = fmaf(dw[k    ], wb[k], bur0);
                bur1 = fmaf(dw[k + 1], wb[k], bur1);
            }
            float2 xcen = *reinterpret_cast<const float2*>(xc + j0 + 12);
            float xm0 = 0.9f * env0 + 0.6f * bur0 + 0.2f * xcen.x;
            float xm1 = 0.9f * env1 + 0.6f * bur1 + 0.2f * xcen.y;
            float wn0 = smem[OFF_WN +  0 + c], wn1 = smem[OFF_WN +  4 + c];
            float wn2 = smem[OFF_WN +  8 + c], wn3 = smem[OFF_WN + 12 + c];
            s00 = fmaf(wn0, xm0, s00); s01 = fmaf(wn0, xm1, s01);
            s10 = fmaf(wn1, xm0, s10); s11 = fmaf(wn1, xm1, s11);
            s20 = fmaf(wn2, xm0, s20); s21 = fmaf(wn2, xm1, s21);
            s30 = fmaf(wn3, xm0, s30); s31 = fmaf(wn3, xm1, s31);
        }
        // reference zero-pads S outside [0,T)
        if ((unsigned)(t0 - 4 + j0) >= (unsigned)T_)     { s00 = s10 = s20 = s30 = 0.f; }
        if ((unsigned)(t0 - 4 + j0 + 1) >= (unsigned)T_) { s01 = s11 = s21 = s31 = 0.f; }
        *reinterpret_cast<float2*>(smem + OFF_S0 + 0*S0LEN + j0) = make_float2(s00, s01);
        *reinterpret_cast<float2*>(smem + OFF_S0 + 1*S0LEN + j0) = make_float2(s10, s11);
        *reinterpret_cast<float2*>(smem + OFF_S0 + 2*S0LEN + j0) = make_float2(s20, s21);
        *reinterpret_cast<float2*>(smem + OFF_S0 + 3*S0LEN + j0) = make_float2(s30, s31);
    }
    __syncthreads();

    // ---- phase 4: dwK9+gelu, pw4x4+gelu, gate; consecutive dual-u --------
    if (tid < 500) {
        const int uA = 2 * tid, uB = uA + 1;
        float g1A[4], g1B[4];
        #pragma unroll
        for (int m = 0; m < 4; m++) {
            const float* s0 = smem + OFF_S0 + m * S0LEN;
            float v[10];
            #pragma unroll
            for (int q = 0; q < 5; q++) {
                float2 t = *reinterpret_cast<const float2*>(s0 + uA + q * 2);
                v[q*2] = t.x; v[q*2+1] = t.y;
            }
            const float* wd = smem + OFF_WDW + m * 12;
            float aA = 0.f, aB = 0.f;
            #pragma unroll
            for (int k = 0; k < 9; k++) {
                float w = wd[k];
                aA = fmaf(v[k    ], w, aA);
                aB = fmaf(v[k + 1], w, aB);
            }
            g1A[m] = gelu_(aA);
            g1B[m] = gelu_(aB);
        }
        float4 smA = reinterpret_cast<const float4*>(smem + OFF_SM)[uA];
        float4 smB = reinterpret_cast<const float4*>(smem + OFF_SM)[uB];
        float sArA[4] = {smA.x, smA.y, smA.z, smA.w};
        float sArB[4] = {smB.x, smB.y, smB.z, smB.w};
        const int pA = uA / 25, jjA = uA - pA * 25;
        const int pB = uB / 25, jjB = uB - pB * 25;
        #pragma unroll
        for (int o = 0; o < 4; o++) {
            float w0 = smem[OFF_WPW + o*4 + 0], w1 = smem[OFF_WPW + o*4 + 1];
            float w2 = smem[OFF_WPW + o*4 + 2], w3 = smem[OFF_WPW + o*4 + 3];
            float aA = w0*g1A[0] + w1*g1A[1] + w2*g1A[2] + w3*g1A[3];
            float aB = w0*g1B[0] + w1*g1B[1] + w2*g1B[2] + w3*g1B[3];
            float xA = gelu_(aA) * sArA[o];
            float xB = gelu_(aB) * sArB[o];
            // duplicated store (v,v) -> MOV-free f32x2 GEMM loads
            *reinterpret_cast<float2*>(smem + OFF_XS2 + (o*25 + jjA) * P2PAD + 2*pA) = make_float2(xA, xA);
            *reinterpret_cast<float2*>(smem + OFF_XS2 + (o*25 + jjB) * P2PAD + 2*pB) = make_float2(xB, xB);
        }
    }
    __syncthreads();

    // ---- phase 5: patch GEMM h[p][d] = sum_k xs[k][p]*wT[k][d] -----------
    // 400 threads: 4 consecutive d x 4 p. Per k: 1 LDS.128 + 4 LDS.64 + 8 FFMA2.
    if (tid < 400) {
        const int d0    = (tid % 40) * 4;
        const int pbase = (tid / 40) * 4;
        unsigned long long acc[4][2];                // [p][dpair]
        #pragma unroll
        for (int j = 0; j < 4; j++) { acc[j][0] = 0ull; acc[j][1] = 0ull; }
        const float* ws  = smem + OFF_WS  + d0;
        const float* xs2 = smem + OFF_XS2 + 2 * pbase;
        #pragma unroll 2
        for (int k = 0; k < 100; k++) {
            const unsigned long long* wp =
                reinterpret_cast<const unsigned long long*>(ws + k * WPADW);
            unsigned long long w01 = wp[0];
            unsigned long long w23 = wp[1];
            unsigned long long x0 = *reinterpret_cast<const unsigned long long*>(xs2 + k * P2PAD);
            unsigned long long x1 = *reinterpret_cast<const unsigned long long*>(xs2 + k * P2PAD + 2);
            unsigned long long x2 = *reinterpret_cast<const unsigned long long*>(xs2 + k * P2PAD + 4);
            unsigned long long x3 = *reinterpret_cast<const unsigned long long*>(xs2 + k * P2PAD + 6);
            fma2_(acc[0][0], w01, x0); fma2_(acc[0][1], w23, x0);
            fma2_(acc[1][0], w01, x1); fma2_(acc[1][1], w23, x1);
            fma2_(acc[2][0], w01, x2); fma2_(acc[2][1], w23, x2);
            fma2_(acc[3][0], w01, x3); fma2_(acc[3][1], w23, x3);
        }
        #pragma unroll
        for (int j = 0; j < 4; j++) {
            float2 lo = upk2_(acc[j][0]);
            float2 hi = upk2_(acc[j][1]);
            *reinterpret_cast<float4*>(smem + OFF_H + (pbase + j) * D_ + d0) =
                make_float4(lo.x, lo.y, hi.x, hi.y);
        }
    }
    __syncthreads();

    // ---- phase 6: LayerNorm(D=160) + m_patch -----------------------------
    const int wid = tid >> 5, lane = tid & 31;
    for (int p = wid; p < NPATCH; p += NTH / 32) {
        const float* hp = smem + OFF_H + p * D_;
        float s = 0.f;
        #pragma unroll
        for (int i = 0; i < 5; i++) s += hp[lane + 32 * i];
        #pragma unroll
        for (int o = 16; o; o >>= 1) s += __shfl_xor_sync(0xffffffffu, s, o);
        float mu = s * (1.f / 160.f);
        float v = 0.f;
        #pragma unroll
        for (int i = 0; i < 5; i++) { float d = hp[lane + 32 * i] - mu; v = fmaf(d, d, v); }
        #pragma unroll
        for (int o = 16; o; o >>= 1) v += __shfl_xor_sync(0xffffffffu, v, o);
        float rstd = rsqrtf(v * (1.f / 160.f) + 1e-5f);
        const int pg = tile * NPATCH + p;
        float* oh = out_h + ((size_t)b * L_ + pg) * D_;
        #pragma unroll
        for (int i = 0; i < 5; i++) {
            int d = lane + 32 * i;
            oh[d] = (hp[d] - mu) * rstd * smem[OFF_G + d] + smem[OFF_BT + d];
        }
        int pred = 0;
        if (lane < 25) {
            float4 q = reinterpret_cast<const float4*>(smem + OFF_SM)[p * 25 + lane];
            pred = (q.x + q.y + q.z + q.w) > 0.f ? 1 : 0;
        }
        unsigned bal = __ballot_sync(0xffffffffu, pred);
        if (lane == 0) {
            int cnt = __popc(bal & 0x1ffffffu);
            out_mp[(size_t)b * L_ + pg] = ((float)cnt * (1.f / 25.f) > 0.1f) ? 1.f : 0.f;
        }
    }
}

extern "C" void kernel_launch(void* const* d_in, const int* in_sizes, int n_in,
                              void* d_out, int out_size) {
    const float* X      = (const float*)d_in[0];
    const float* M      = (const float*)d_in[1];
    const float* w_env  = (const float*)d_in[2];
    const float* w_bur  = (const float*)d_in[3];
    const float* syn    = (const float*)d_in[4];
    const float* w_dw   = (const float*)d_in[5];
    const float* w_pw   = (const float*)d_in[6];
    const float* w_proj = (const float*)d_in[7];
    const float* gam    = (const float*)d_in[8];
    const float* bet    = (const float*)d_in[9];

    float* out_h  = (float*)d_out;
    float* out_mp = out_h + (size_t)B_ * L_ * D_;

    cudaFuncSetAttribute(emg_fused_kernel,
                         cudaFuncAttributeMaxDynamicSharedMemorySize,
                         SMEM_FLOATS * (int)sizeof(float));

    emg_fused_kernel<<<B_ * TPB, NTH, SMEM_FLOATS * (int)sizeof(float)>>>(
        X, M, w_env, w_bur, syn, w_dw, w_pw, w_proj, gam, bet, out_h, out_mp);
}

// round 12
// speedup vs baseline: 1.5113x; 1.0623x over previous
#include <cuda_runtime.h>
#include <math.h>

// ---------------------------------------------------------------------------
// EMG_SyEMB fused kernel, sm_103a. R11: TILE=500 + 110.9KB smem -> 2 CTAs/SM
// (32 warps). |dx| computed in registers (no ADX array), H aliases dead SX/S0,
// MOV-free f32x2 GEMM. One block = (batch b, 20-patch half-tile).
// ---------------------------------------------------------------------------

namespace {
constexpr int B_ = 64, T_ = 50000, C_ = 4, D_ = 160, P_ = 25, L_ = 2000;
constexpr int TILE   = 500;
constexpr int NPATCH = TILE / P_;      // 20
constexpr int HALO   = 16;
constexpr int XLEN   = TILE + 2*HALO;  // 532
constexpr int S0LEN  = TILE + 8;       // 508
constexpr int NTH    = 512;
constexpr int TPB    = L_ / NPATCH;    // 100
constexpr int WPADW  = 164;            // WS row stride (d), %4==0 for float4
constexpr int P2PAD  = 46;             // XS2 row stride (2p dup), 2-way store conflicts

constexpr int OFF_SX   = 0;                      // [4][532]  (aliased by H in ph5)
constexpr int OFF_S0   = OFF_SX  + 4*XLEN;       // [4][508]  (aliased by H in ph5)
constexpr int OFF_SM   = OFF_S0  + 4*S0LEN;      // [500][4]
constexpr int OFF_XS2  = OFF_SM  + TILE*4;       // [100][46] xs duplicated (v,v)
constexpr int OFF_WS   = OFF_XS2 + 100*P2PAD;    // [100][164]
constexpr int OFF_WENV = OFF_WS  + 100*WPADW;    // [4][28] padded
constexpr int OFF_WBUR = OFF_WENV + 112;         // [4][12] padded
constexpr int OFF_WDW  = OFF_WBUR + 48;          // [4][12] padded
constexpr int OFF_WPW  = OFF_WDW  + 48;          // [4][4]
constexpr int OFF_WN   = OFF_WPW  + 16;          // [4][4]
constexpr int OFF_G    = OFF_WN   + 16;          // [160]
constexpr int OFF_BT   = OFF_G    + D_;          // [160]
constexpr int SMEM_FLOATS = OFF_BT + D_;         // 27720 floats = 110880 B
constexpr int OFF_H    = 0;                      // [20][160]=3200, aliases SX+S0 (4160)
}

__device__ __forceinline__ float gelu_(float x) {
    return 0.5f * x * (1.0f + erff(x * 0.70710678118654752440f));
}

// packed fp32x2 helpers (sm_103a FFMA2 — only reachable via PTX)
__device__ __forceinline__ void fma2_(unsigned long long& d,
                                      unsigned long long a, unsigned long long b) {
    asm("fma.rn.f32x2 %0, %1, %2, %0;" : "+l"(d) : "l"(a), "l"(b));
}
__device__ __forceinline__ float2 upk2_(unsigned long long v) {
    float2 r;
    asm("mov.b64 {%0, %1}, %2;" : "=f"(r.x), "=f"(r.y) : "l"(v));
    return r;
}

__global__ void __launch_bounds__(NTH, 2)
emg_fused_kernel(const float* __restrict__ X,  const float* __restrict__ Mk,
                 const float* __restrict__ w_env, const float* __restrict__ w_bur,
                 const float* __restrict__ syn,   const float* __restrict__ w_dw,
                 const float* __restrict__ w_pw,  const float* __restrict__ w_proj,
                 const float* __restrict__ gam,   const float* __restrict__ bet,
                 float* __restrict__ out_h, float* __restrict__ out_mp)
{
    extern __shared__ float smem[];
    const int tid  = threadIdx.x;
    const int b    = blockIdx.x / TPB;
    const int tile = blockIdx.x % TPB;
    const int t0   = tile * TILE;

    // ---- weights to smem --------------------------------------------------
    for (int i = tid; i < D_ * 100; i += NTH) {
        int d = i / 100, k = i - d * 100;
        smem[OFF_WS + k * WPADW + d] = w_proj[i];
    }
    for (int i = tid; i < 112; i += NTH) {
        int c = i / 28, k = i - c * 28;
        smem[OFF_WENV + i] = (k < 25) ? w_env[c * 25 + k] : 0.f;
    }
    for (int i = tid; i < 48; i += NTH) {
        int c = i / 12, k = i - c * 12;
        smem[OFF_WBUR + i] = (k < 9) ? w_bur[c * 9 + k] : 0.f;
        smem[OFF_WDW  + i] = (k < 9) ? w_dw [c * 9 + k] : 0.f;
    }
    for (int i = tid; i < 16;  i += NTH) smem[OFF_WPW + i] = w_pw[i];
    for (int i = tid; i < D_;  i += NTH) { smem[OFF_G + i] = gam[i]; smem[OFF_BT + i] = bet[i]; }
    if (tid == 0) {
        float sp[16];
        for (int m = 0; m < 4; m++) {
            float s = 0.f;
            for (int c = 0; c < 4; c++) {
                float x = syn[m * 4 + c];
                float v = (x > 20.f) ? x : log1pf(expf(x));
                sp[m * 4 + c] = v; s += v;
            }
            float inv = 1.f / fmaxf(s, 1e-6f);
            for (int c = 0; c < 4; c++) smem[OFF_WN + m * 4 + c] = sp[m * 4 + c] * inv;
        }
    }
    __syncthreads();

    // ---- phase 1: x = X*M (halo), Sm = clip(W@(M>0),0,1) ------------------
    const float4* Xb = reinterpret_cast<const float4*>(X)  + (size_t)b * T_;
    const float4* Mb = reinterpret_cast<const float4*>(Mk) + (size_t)b * T_;
    for (int tt = tid; tt < XLEN; tt += NTH) {
        int g = t0 - HALO + tt;
        float x0 = 0.f, x1 = 0.f, x2 = 0.f, x3 = 0.f;
        if ((unsigned)g < (unsigned)T_) {
            float4 xv = Xb[g];
            float4 mv = Mb[g];
            x0 = xv.x * mv.x; x1 = xv.y * mv.y; x2 = xv.z * mv.z; x3 = xv.w * mv.w;
            int u = tt - HALO;
            if ((unsigned)u < (unsigned)TILE) {
                float m0 = mv.x > 0.f ? 1.f : 0.f, m1 = mv.y > 0.f ? 1.f : 0.f;
                float m2 = mv.z > 0.f ? 1.f : 0.f, m3 = mv.w > 0.f ? 1.f : 0.f;
                float4 s;
                s.x = fminf(fmaxf(smem[OFF_WN+ 0]*m0 + smem[OFF_WN+ 1]*m1 + smem[OFF_WN+ 2]*m2 + smem[OFF_WN+ 3]*m3, 0.f), 1.f);
                s.y = fminf(fmaxf(smem[OFF_WN+ 4]*m0 + smem[OFF_WN+ 5]*m1 + smem[OFF_WN+ 6]*m2 + smem[OFF_WN+ 7]*m3, 0.f), 1.f);
                s.z = fminf(fmaxf(smem[OFF_WN+ 8]*m0 + smem[OFF_WN+ 9]*m1 + smem[OFF_WN+10]*m2 + smem[OFF_WN+11]*m3, 0.f), 1.f);
                s.w = fminf(fmaxf(smem[OFF_WN+12]*m0 + smem[OFF_WN+13]*m1 + smem[OFF_WN+14]*m2 + smem[OFF_WN+15]*m3, 0.f), 1.f);
                reinterpret_cast<float4*>(smem + OFF_SM)[u] = s;
            }
        }
        smem[OFF_SX + 0*XLEN + tt] = x0;
        smem[OFF_SX + 1*XLEN + tt] = x1;
        smem[OFF_SX + 2*XLEN + tt] = x2;
        smem[OFF_SX + 3*XLEN + tt] = x3;
    }
    __syncthreads();

    // ---- phase 2+3: S0 = W @ (.9 env + .6 burst + .2 x), dual-j ----------
    // 254 threads, j0=2*tid. Signed x window in regs (13 LDS.64); |x| via
    // inline FABS; |dx| derived from the same window with boundary predicates;
    // weights streamed as broadcast LDS. Live set ~45 floats (no spill @64).
    if (tid < 254) {
        const int j0 = 2 * tid;
        float s00 = 0.f, s01 = 0.f, s10 = 0.f, s11 = 0.f;
        float s20 = 0.f, s21 = 0.f, s30 = 0.f, s31 = 0.f;
        #pragma unroll 1
        for (int c = 0; c < 4; c++) {
            const float* xc = smem + OFF_SX + c * XLEN;
            float xw[26];
            #pragma unroll
            for (int q = 0; q < 13; q++) {
                float2 t = *reinterpret_cast<const float2*>(xc + j0 + 2 * q);
                xw[2*q] = t.x; xw[2*q+1] = t.y;
            }
            const float* we = smem + OFF_WENV + c * 28;
            float env0 = 0.f, env1 = 0.f;
            #pragma unroll
            for (int k = 0; k < 25; k++) {
                float w = we[k];
                env0 = fmaf(fabsf(xw[k    ]), w, env0);
                env1 = fmaf(fabsf(xw[k + 1]), w, env1);
            }
            const float* wb = smem + OFF_WBUR + c * 12;
            float bur0 = 0.f, bur1 = 0.f;
            #pragma unroll
            for (int k = 0; k < 9; k++) {
                float w = wb[k];
                // dx at global gg = t0 + j0 - 8 + k (and gg+1); dx=0 unless 1<=gg<T
                int gg = t0 + j0 - 8 + k;
                float d0v = (gg   >= 1 && gg   < T_) ? fabsf(xw[k + 8] - xw[k + 7]) : 0.f;
                float d1v = (gg+1 >= 1 && gg+1 < T_) ? fabsf(xw[k + 9] - xw[k + 8]) : 0.f;
                bur0 = fmaf(d0v, w, bur0);
                bur1 = fmaf(d1v, w, bur1);
            }
            float xm0 = 0.9f * env0 + 0.6f * bur0 + 0.2f * xw[12];
            float xm1 = 0.9f * env1 + 0.6f * bur1 + 0.2f * xw[13];
            float wn0 = smem[OFF_WN +  0 + c], wn1 = smem[OFF_WN +  4 + c];
            float wn2 = smem[OFF_WN +  8 + c], wn3 = smem[OFF_WN + 12 + c];
            s00 = fmaf(wn0, xm0, s00); s01 = fmaf(wn0, xm1, s01);
            s10 = fmaf(wn1, xm0, s10); s11 = fmaf(wn1, xm1, s11);
            s20 = fmaf(wn2, xm0, s20); s21 = fmaf(wn2, xm1, s21);
            s30 = fmaf(wn3, xm0, s30); s31 = fmaf(wn3, xm1, s31);
        }
        // reference zero-pads S outside [0,T)
        if ((unsigned)(t0 - 4 + j0)     >= (unsigned)T_) { s00 = s10 = s20 = s30 = 0.f; }
        if ((unsigned)(t0 - 4 + j0 + 1) >= (unsigned)T_) { s01 = s11 = s21 = s31 = 0.f; }
        *reinterpret_cast<float2*>(smem + OFF_S0 + 0*S0LEN + j0) = make_float2(s00, s01);
        *reinterpret_cast<float2*>(smem + OFF_S0 + 1*S0LEN + j0) = make_float2(s10, s11);
        *reinterpret_cast<float2*>(smem + OFF_S0 + 2*S0LEN + j0) = make_float2(s20, s21);
        *reinterpret_cast<float2*>(smem + OFF_S0 + 3*S0LEN + j0) = make_float2(s30, s31);
    }
    __syncthreads();

    // ---- phase 4: dwK9+gelu, pw4x4+gelu, gate; dual-u --------------------
    if (tid < 250) {
        const int uA = 2 * tid, uB = uA + 1;
        float g1A[4], g1B[4];
        #pragma unroll
        for (int m = 0; m < 4; m++) {
            const float* s0 = smem + OFF_S0 + m * S0LEN;
            float v[10];
            #pragma unroll
            for (int q = 0; q < 5; q++) {
                float2 t = *reinterpret_cast<const float2*>(s0 + uA + q * 2);
                v[q*2] = t.x; v[q*2+1] = t.y;
            }
            const float* wd = smem + OFF_WDW + m * 12;
            float aA = 0.f, aB = 0.f;
            #pragma unroll
            for (int k = 0; k < 9; k++) {
                float w = wd[k];
                aA = fmaf(v[k    ], w, aA);
                aB = fmaf(v[k + 1], w, aB);
            }
            g1A[m] = gelu_(aA);
            g1B[m] = gelu_(aB);
        }
        float4 smA = reinterpret_cast<const float4*>(smem + OFF_SM)[uA];
        float4 smB = reinterpret_cast<const float4*>(smem + OFF_SM)[uB];
        float sArA[4] = {smA.x, smA.y, smA.z, smA.w};
        float sArB[4] = {smB.x, smB.y, smB.z, smB.w};
        const int pA = uA / 25, jjA = uA - pA * 25;
        const int pB = uB / 25, jjB = uB - pB * 25;
        #pragma unroll
        for (int o = 0; o < 4; o++) {
            float w0 = smem[OFF_WPW + o*4 + 0], w1 = smem[OFF_WPW + o*4 + 1];
            float w2 = smem[OFF_WPW + o*4 + 2], w3 = smem[OFF_WPW + o*4 + 3];
            float aA = w0*g1A[0] + w1*g1A[1] + w2*g1A[2] + w3*g1A[3];
            float aB = w0*g1B[0] + w1*g1B[1] + w2*g1B[2] + w3*g1B[3];
            float xA = gelu_(aA) * sArA[o];
            float xB = gelu_(aB) * sArB[o];
            *reinterpret_cast<float2*>(smem + OFF_XS2 + (o*25 + jjA) * P2PAD + 2*pA) = make_float2(xA, xA);
            *reinterpret_cast<float2*>(smem + OFF_XS2 + (o*25 + jjB) * P2PAD + 2*pB) = make_float2(xB, xB);
        }
    }
    __syncthreads();

    // ---- phase 5: patch GEMM h[p][d] = sum_k xs[k][p]*wT[k][d] -----------
    // 400 threads: 4 consecutive d x 2 p. Per k: 2 LDS.64(w) + 2 LDS.64(xs,
    // broadcast) + 4 FFMA2. H written into dead SX/S0 region (OFF_H=0).
    if (tid < 400) {
        const int d0    = (tid % 40) * 4;
        const int pbase = (tid / 40) * 2;
        unsigned long long acc[2][2];                // [p][dpair]
        #pragma unroll
        for (int j = 0; j < 2; j++) { acc[j][0] = 0ull; acc[j][1] = 0ull; }
        const float* ws  = smem + OFF_WS  + d0;
        const float* xs2 = smem + OFF_XS2 + 2 * pbase;
        #pragma unroll 2
        for (int k = 0; k < 100; k++) {
            const unsigned long long* wp =
                reinterpret_cast<const unsigned long long*>(ws + k * WPADW);
            unsigned long long w01 = wp[0];
            unsigned long long w23 = wp[1];
            unsigned long long x0 = *reinterpret_cast<const unsigned long long*>(xs2 + k * P2PAD);
            unsigned long long x1 = *reinterpret_cast<const unsigned long long*>(xs2 + k * P2PAD + 2);
            fma2_(acc[0][0], w01, x0); fma2_(acc[0][1], w23, x0);
            fma2_(acc[1][0], w01, x1); fma2_(acc[1][1], w23, x1);
        }
        #pragma unroll
        for (int j = 0; j < 2; j++) {
            float2 lo = upk2_(acc[j][0]);
            float2 hi = upk2_(acc[j][1]);
            *reinterpret_cast<float4*>(smem + OFF_H + (pbase + j) * D_ + d0) =
                make_float4(lo.x, lo.y, hi.x, hi.y);
        }
    }
    __syncthreads();

    // ---- phase 6: LayerNorm(D=160) + m_patch -----------------------------
    const int wid = tid >> 5, lane = tid & 31;
    for (int p = wid; p < NPATCH; p += NTH / 32) {
        const float* hp = smem + OFF_H + p * D_;
        float s = 0.f;
        #pragma unroll
        for (int i = 0; i < 5; i++) s += hp[lane + 32 * i];
        #pragma unroll
        for (int o = 16; o; o >>= 1) s += __shfl_xor_sync(0xffffffffu, s, o);
        float mu = s * (1.f / 160.f);
        float v = 0.f;
        #pragma unroll
        for (int i = 0; i < 5; i++) { float d = hp[lane + 32 * i] - mu; v = fmaf(d, d, v); }
        #pragma unroll
        for (int o = 16; o; o >>= 1) v += __shfl_xor_sync(0xffffffffu, v, o);
        float rstd = rsqrtf(v * (1.f / 160.f) + 1e-5f);
        const int pg = tile * NPATCH + p;
        float* oh = out_h + ((size_t)b * L_ + pg) * D_;
        #pragma unroll
        for (int i = 0; i < 5; i++) {
            int d = lane + 32 * i;
            oh[d] = (hp[d] - mu) * rstd * smem[OFF_G + d] + smem[OFF_BT + d];
        }
        int pred = 0;
        if (lane < 25) {
            float4 q = reinterpret_cast<const float4*>(smem + OFF_SM)[p * 25 + lane];
            pred = (q.x + q.y + q.z + q.w) > 0.f ? 1 : 0;
        }
        unsigned bal = __ballot_sync(0xffffffffu, pred);
        if (lane == 0) {
            int cnt = __popc(bal & 0x1ffffffu);
            out_mp[(size_t)b * L_ + pg] = ((float)cnt * (1.f / 25.f) > 0.1f) ? 1.f : 0.f;
        }
    }
}

extern "C" void kernel_launch(void* const* d_in, const int* in_sizes, int n_in,
                              void* d_out, int out_size) {
    const float* X      = (const float*)d_in[0];
    const float* M      = (const float*)d_in[1];
    const float* w_env  = (const float*)d_in[2];
    const float* w_bur  = (const float*)d_in[3];
    const float* syn    = (const float*)d_in[4];
    const float* w_dw   = (const float*)d_in[5];
    const float* w_pw   = (const float*)d_in[6];
    const float* w_proj = (const float*)d_in[7];
    const float* gam    = (const float*)d_in[8];
    const float* bet    = (const float*)d_in[9];

    float* out_h  = (float*)d_out;
    float* out_mp = out_h + (size_t)B_ * L_ * D_;

    cudaFuncSetAttribute(emg_fused_kernel,
                         cudaFuncAttributeMaxDynamicSharedMemorySize,
                         SMEM_FLOATS * (int)sizeof(float));

    emg_fused_kernel<<<B_ * TPB, NTH, SMEM_FLOATS * (int)sizeof(float)>>>(
        X, M, w_env, w_bur, syn, w_dw, w_pw, w_proj, gam, bet, out_h, out_mp);
}

// round 13
// speedup vs baseline: 1.6708x; 1.1056x over previous
#include <cuda_runtime.h>
#include <math.h>

// ---------------------------------------------------------------------------
// EMG_SyEMB fused kernel, sm_103a. R13: R12 (TILE=500, 2 CTAs/SM) with the
// patch GEMM restructured to 200 threads x (4d x 4p), LDS.128 weight loads:
// ~2.5x fewer LDS wavefronts in the dominant phase.
// ---------------------------------------------------------------------------

namespace {
constexpr int B_ = 64, T_ = 50000, C_ = 4, D_ = 160, P_ = 25, L_ = 2000;
constexpr int TILE   = 500;
constexpr int NPATCH = TILE / P_;      // 20
constexpr int HALO   = 16;
constexpr int XLEN   = TILE + 2*HALO;  // 532
constexpr int S0LEN  = TILE + 8;       // 508
constexpr int NTH    = 512;
constexpr int TPB    = L_ / NPATCH;    // 100
constexpr int WPADW  = 164;            // WS row stride (d), %4==0 for LDS.128
constexpr int P2PAD  = 46;             // XS2 row stride (2p dup), 2-way store conflicts

constexpr int OFF_SX   = 0;                      // [4][532]  (aliased by H in ph5)
constexpr int OFF_S0   = OFF_SX  + 4*XLEN;       // [4][508]  (aliased by H in ph5)
constexpr int OFF_SM   = OFF_S0  + 4*S0LEN;      // [500][4]
constexpr int OFF_XS2  = OFF_SM  + TILE*4;       // [100][46] xs duplicated (v,v)
constexpr int OFF_WS   = OFF_XS2 + 100*P2PAD;    // [100][164]
constexpr int OFF_WENV = OFF_WS  + 100*WPADW;    // [4][28] padded
constexpr int OFF_WBUR = OFF_WENV + 112;         // [4][12] padded
constexpr int OFF_WDW  = OFF_WBUR + 48;          // [4][12] padded
constexpr int OFF_WPW  = OFF_WDW  + 48;          // [4][4]
constexpr int OFF_WN   = OFF_WPW  + 16;          // [4][4]
constexpr int OFF_G    = OFF_WN   + 16;          // [160]
constexpr int OFF_BT   = OFF_G    + D_;          // [160]
constexpr int SMEM_FLOATS = OFF_BT + D_;         // 27720 floats = 110880 B
constexpr int OFF_H    = 0;                      // [20][160]=3200, aliases SX+S0 (4160)
}

__device__ __forceinline__ float gelu_(float x) {
    return 0.5f * x * (1.0f + erff(x * 0.70710678118654752440f));
}

// packed fp32x2 helpers (sm_103a FFMA2 — only reachable via PTX)
__device__ __forceinline__ void fma2_(unsigned long long& d,
                                      unsigned long long a, unsigned long long b) {
    asm("fma.rn.f32x2 %0, %1, %2, %0;" : "+l"(d) : "l"(a), "l"(b));
}
__device__ __forceinline__ float2 upk2_(unsigned long long v) {
    float2 r;
    asm("mov.b64 {%0, %1}, %2;" : "=f"(r.x), "=f"(r.y) : "l"(v));
    return r;
}

__global__ void __launch_bounds__(NTH, 2)
emg_fused_kernel(const float* __restrict__ X,  const float* __restrict__ Mk,
                 const float* __restrict__ w_env, const float* __restrict__ w_bur,
                 const float* __restrict__ syn,   const float* __restrict__ w_dw,
                 const float* __restrict__ w_pw,  const float* __restrict__ w_proj,
                 const float* __restrict__ gam,   const float* __restrict__ bet,
                 float* __restrict__ out_h, float* __restrict__ out_mp)
{
    extern __shared__ float smem[];
    const int tid  = threadIdx.x;
    const int b    = blockIdx.x / TPB;
    const int tile = blockIdx.x % TPB;
    const int t0   = tile * TILE;

    // ---- weights to smem --------------------------------------------------
    for (int i = tid; i < D_ * 100; i += NTH) {
        int d = i / 100, k = i - d * 100;
        smem[OFF_WS + k * WPADW + d] = w_proj[i];
    }
    for (int i = tid; i < 112; i += NTH) {
        int c = i / 28, k = i - c * 28;
        smem[OFF_WENV + i] = (k < 25) ? w_env[c * 25 + k] : 0.f;
    }
    for (int i = tid; i < 48; i += NTH) {
        int c = i / 12, k = i - c * 12;
        smem[OFF_WBUR + i] = (k < 9) ? w_bur[c * 9 + k] : 0.f;
        smem[OFF_WDW  + i] = (k < 9) ? w_dw [c * 9 + k] : 0.f;
    }
    for (int i = tid; i < 16;  i += NTH) smem[OFF_WPW + i] = w_pw[i];
    for (int i = tid; i < D_;  i += NTH) { smem[OFF_G + i] = gam[i]; smem[OFF_BT + i] = bet[i]; }
    if (tid == 0) {
        float sp[16];
        for (int m = 0; m < 4; m++) {
            float s = 0.f;
            for (int c = 0; c < 4; c++) {
                float x = syn[m * 4 + c];
                float v = (x > 20.f) ? x : log1pf(expf(x));
                sp[m * 4 + c] = v; s += v;
            }
            float inv = 1.f / fmaxf(s, 1e-6f);
            for (int c = 0; c < 4; c++) smem[OFF_WN + m * 4 + c] = sp[m * 4 + c] * inv;
        }
    }
    __syncthreads();

    // ---- phase 1: x = X*M (halo), Sm = clip(W@(M>0),0,1) ------------------
    const float4* Xb = reinterpret_cast<const float4*>(X)  + (size_t)b * T_;
    const float4* Mb = reinterpret_cast<const float4*>(Mk) + (size_t)b * T_;
    for (int tt = tid; tt < XLEN; tt += NTH) {
        int g = t0 - HALO + tt;
        float x0 = 0.f, x1 = 0.f, x2 = 0.f, x3 = 0.f;
        if ((unsigned)g < (unsigned)T_) {
            float4 xv = Xb[g];
            float4 mv = Mb[g];
            x0 = xv.x * mv.x; x1 = xv.y * mv.y; x2 = xv.z * mv.z; x3 = xv.w * mv.w;
            int u = tt - HALO;
            if ((unsigned)u < (unsigned)TILE) {
                float m0 = mv.x > 0.f ? 1.f : 0.f, m1 = mv.y > 0.f ? 1.f : 0.f;
                float m2 = mv.z > 0.f ? 1.f : 0.f, m3 = mv.w > 0.f ? 1.f : 0.f;
                float4 s;
                s.x = fminf(fmaxf(smem[OFF_WN+ 0]*m0 + smem[OFF_WN+ 1]*m1 + smem[OFF_WN+ 2]*m2 + smem[OFF_WN+ 3]*m3, 0.f), 1.f);
                s.y = fminf(fmaxf(smem[OFF_WN+ 4]*m0 + smem[OFF_WN+ 5]*m1 + smem[OFF_WN+ 6]*m2 + smem[OFF_WN+ 7]*m3, 0.f), 1.f);
                s.z = fminf(fmaxf(smem[OFF_WN+ 8]*m0 + smem[OFF_WN+ 9]*m1 + smem[OFF_WN+10]*m2 + smem[OFF_WN+11]*m3, 0.f), 1.f);
                s.w = fminf(fmaxf(smem[OFF_WN+12]*m0 + smem[OFF_WN+13]*m1 + smem[OFF_WN+14]*m2 + smem[OFF_WN+15]*m3, 0.f), 1.f);
                reinterpret_cast<float4*>(smem + OFF_SM)[u] = s;
            }
        }
        smem[OFF_SX + 0*XLEN + tt] = x0;
        smem[OFF_SX + 1*XLEN + tt] = x1;
        smem[OFF_SX + 2*XLEN + tt] = x2;
        smem[OFF_SX + 3*XLEN + tt] = x3;
    }
    __syncthreads();

    // ---- phase 2+3: S0 = W @ (.9 env + .6 burst + .2 x), dual-j ----------
    if (tid < 254) {
        const int j0 = 2 * tid;
        float s00 = 0.f, s01 = 0.f, s10 = 0.f, s11 = 0.f;
        float s20 = 0.f, s21 = 0.f, s30 = 0.f, s31 = 0.f;
        #pragma unroll 1
        for (int c = 0; c < 4; c++) {
            const float* xc = smem + OFF_SX + c * XLEN;
            float xw[26];
            #pragma unroll
            for (int q = 0; q < 13; q++) {
                float2 t = *reinterpret_cast<const float2*>(xc + j0 + 2 * q);
                xw[2*q] = t.x; xw[2*q+1] = t.y;
            }
            const float* we = smem + OFF_WENV + c * 28;
            float env0 = 0.f, env1 = 0.f;
            #pragma unroll
            for (int k = 0; k < 25; k++) {
                float w = we[k];
                env0 = fmaf(fabsf(xw[k    ]), w, env0);
                env1 = fmaf(fabsf(xw[k + 1]), w, env1);
            }
            const float* wb = smem + OFF_WBUR + c * 12;
            float bur0 = 0.f, bur1 = 0.f;
            #pragma unroll
            for (int k = 0; k < 9; k++) {
                float w = wb[k];
                int gg = t0 + j0 - 8 + k;
                float d0v = (gg   >= 1 && gg   < T_) ? fabsf(xw[k + 8] - xw[k + 7]) : 0.f;
                float d1v = (gg+1 >= 1 && gg+1 < T_) ? fabsf(xw[k + 9] - xw[k + 8]) : 0.f;
                bur0 = fmaf(d0v, w, bur0);
                bur1 = fmaf(d1v, w, bur1);
            }
            float xm0 = 0.9f * env0 + 0.6f * bur0 + 0.2f * xw[12];
            float xm1 = 0.9f * env1 + 0.6f * bur1 + 0.2f * xw[13];
            float wn0 = smem[OFF_WN +  0 + c], wn1 = smem[OFF_WN +  4 + c];
            float wn2 = smem[OFF_WN +  8 + c], wn3 = smem[OFF_WN + 12 + c];
            s00 = fmaf(wn0, xm0, s00); s01 = fmaf(wn0, xm1, s01);
            s10 = fmaf(wn1, xm0, s10); s11 = fmaf(wn1, xm1, s11);
            s20 = fmaf(wn2, xm0, s20); s21 = fmaf(wn2, xm1, s21);
            s30 = fmaf(wn3, xm0, s30); s31 = fmaf(wn3, xm1, s31);
        }
        if ((unsigned)(t0 - 4 + j0)     >= (unsigned)T_) { s00 = s10 = s20 = s30 = 0.f; }
        if ((unsigned)(t0 - 4 + j0 + 1) >= (unsigned)T_) { s01 = s11 = s21 = s31 = 0.f; }
        *reinterpret_cast<float2*>(smem + OFF_S0 + 0*S0LEN + j0) = make_float2(s00, s01);
        *reinterpret_cast<float2*>(smem + OFF_S0 + 1*S0LEN + j0) = make_float2(s10, s11);
        *reinterpret_cast<float2*>(smem + OFF_S0 + 2*S0LEN + j0) = make_float2(s20, s21);
        *reinterpret_cast<float2*>(smem + OFF_S0 + 3*S0LEN + j0) = make_float2(s30, s31);
    }
    __syncthreads();

    // ---- phase 4: dwK9+gelu, pw4x4+gelu, gate; dual-u --------------------
    if (tid < 250) {
        const int uA = 2 * tid, uB = uA + 1;
        float g1A[4], g1B[4];
        #pragma unroll
        for (int m = 0; m < 4; m++) {
            const float* s0 = smem + OFF_S0 + m * S0LEN;
            float v[10];
            #pragma unroll
            for (int q = 0; q < 5; q++) {
                float2 t = *reinterpret_cast<const float2*>(s0 + uA + q * 2);
                v[q*2] = t.x; v[q*2+1] = t.y;
            }
            const float* wd = smem + OFF_WDW + m * 12;
            float aA = 0.f, aB = 0.f;
            #pragma unroll
            for (int k = 0; k < 9; k++) {
                float w = wd[k];
                aA = fmaf(v[k    ], w, aA);
                aB = fmaf(v[k + 1], w, aB);
            }
            g1A[m] = gelu_(aA);
            g1B[m] = gelu_(aB);
        }
        float4 smA = reinterpret_cast<const float4*>(smem + OFF_SM)[uA];
        float4 smB = reinterpret_cast<const float4*>(smem + OFF_SM)[uB];
        float sArA[4] = {smA.x, smA.y, smA.z, smA.w};
        float sArB[4] = {smB.x, smB.y, smB.z, smB.w};
        const int pA = uA / 25, jjA = uA - pA * 25;
        const int pB = uB / 25, jjB = uB - pB * 25;
        #pragma unroll
        for (int o = 0; o < 4; o++) {
            float w0 = smem[OFF_WPW + o*4 + 0], w1 = smem[OFF_WPW + o*4 + 1];
            float w2 = smem[OFF_WPW + o*4 + 2], w3 = smem[OFF_WPW + o*4 + 3];
            float aA = w0*g1A[0] + w1*g1A[1] + w2*g1A[2] + w3*g1A[3];
            float aB = w0*g1B[0] + w1*g1B[1] + w2*g1B[2] + w3*g1B[3];
            float xA = gelu_(aA) * sArA[o];
            float xB = gelu_(aB) * sArB[o];
            *reinterpret_cast<float2*>(smem + OFF_XS2 + (o*25 + jjA) * P2PAD + 2*pA) = make_float2(xA, xA);
            *reinterpret_cast<float2*>(smem + OFF_XS2 + (o*25 + jjB) * P2PAD + 2*pB) = make_float2(xB, xB);
        }
    }
    __syncthreads();

    // ---- phase 5: patch GEMM h[p][d] = sum_k xs[k][p]*wT[k][d] -----------
    // 200 threads: 4 consecutive d (one LDS.128) x 4 p (broadcast LDS.64).
    // Per k per warp: 4 wf (w) + 4 wf (xs) vs R12's ~10 wf.
    if (tid < 200) {
        const int d0    = (tid % 40) * 4;
        const int pbase = (tid / 40) * 4;        // 5 p-groups x 4 patches
        unsigned long long acc[4][2];            // [p][dpair]
        #pragma unroll
        for (int j = 0; j < 4; j++) { acc[j][0] = 0ull; acc[j][1] = 0ull; }
        const float* ws  = smem + OFF_WS  + d0;
        const float* xs2 = smem + OFF_XS2 + 2 * pbase;
        #pragma unroll 2
        for (int k = 0; k < 100; k++) {
            const ulonglong2 w =
                *reinterpret_cast<const ulonglong2*>(ws + k * WPADW);   // LDS.128
            unsigned long long x0 = *reinterpret_cast<const unsigned long long*>(xs2 + k * P2PAD);
            unsigned long long x1 = *reinterpret_cast<const unsigned long long*>(xs2 + k * P2PAD + 2);
            unsigned long long x2 = *reinterpret_cast<const unsigned long long*>(xs2 + k * P2PAD + 4);
            unsigned long long x3 = *reinterpret_cast<const unsigned long long*>(xs2 + k * P2PAD + 6);
            fma2_(acc[0][0], w.x, x0); fma2_(acc[0][1], w.y, x0);
            fma2_(acc[1][0], w.x, x1); fma2_(acc[1][1], w.y, x1);
            fma2_(acc[2][0], w.x, x2); fma2_(acc[2][1], w.y, x2);
            fma2_(acc[3][0], w.x, x3); fma2_(acc[3][1], w.y, x3);
        }
        #pragma unroll
        for (int j = 0; j < 4; j++) {
            float2 lo = upk2_(acc[j][0]);
            float2 hi = upk2_(acc[j][1]);
            *reinterpret_cast<float4*>(smem + OFF_H + (pbase + j) * D_ + d0) =
                make_float4(lo.x, lo.y, hi.x, hi.y);
        }
    }
    __syncthreads();

    // ---- phase 6: LayerNorm(D=160) + m_patch -----------------------------
    const int wid = tid >> 5, lane = tid & 31;
    for (int p = wid; p < NPATCH; p += NTH / 32) {
        const float* hp = smem + OFF_H + p * D_;
        float s = 0.f;
        #pragma unroll
        for (int i = 0; i < 5; i++) s += hp[lane + 32 * i];
        #pragma unroll
        for (int o = 16; o; o >>= 1) s += __shfl_xor_sync(0xffffffffu, s, o);
        float mu = s * (1.f / 160.f);
        float v = 0.f;
        #pragma unroll
        for (int i = 0; i < 5; i++) { float d = hp[lane + 32 * i] - mu; v = fmaf(d, d, v); }
        #pragma unroll
        for (int o = 16; o; o >>= 1) v += __shfl_xor_sync(0xffffffffu, v, o);
        float rstd = rsqrtf(v * (1.f / 160.f) + 1e-5f);
        const int pg = tile * NPATCH + p;
        float* oh = out_h + ((size_t)b * L_ + pg) * D_;
        #pragma unroll
        for (int i = 0; i < 5; i++) {
            int d = lane + 32 * i;
            oh[d] = (hp[d] - mu) * rstd * smem[OFF_G + d] + smem[OFF_BT + d];
        }
        int pred = 0;
        if (lane < 25) {
            float4 q = reinterpret_cast<const float4*>(smem + OFF_SM)[p * 25 + lane];
            pred = (q.x + q.y + q.z + q.w) > 0.f ? 1 : 0;
        }
        unsigned bal = __ballot_sync(0xffffffffu, pred);
        if (lane == 0) {
            int cnt = __popc(bal & 0x1ffffffu);
            out_mp[(size_t)b * L_ + pg] = ((float)cnt * (1.f / 25.f) > 0.1f) ? 1.f : 0.f;
        }
    }
}

extern "C" void kernel_launch(void* const* d_in, const int* in_sizes, int n_in,
                              void* d_out, int out_size) {
    const float* X      = (const float*)d_in[0];
    const float* M      = (const float*)d_in[1];
    const float* w_env  = (const float*)d_in[2];
    const float* w_bur  = (const float*)d_in[3];
    const float* syn    = (const float*)d_in[4];
    const float* w_dw   = (const float*)d_in[5];
    const float* w_pw   = (const float*)d_in[6];
    const float* w_proj = (const float*)d_in[7];
    const float* gam    = (const float*)d_in[8];
    const float* bet    = (const float*)d_in[9];

    float* out_h  = (float*)d_out;
    float* out_mp = out_h + (size_t)B_ * L_ * D_;

    cudaFuncSetAttribute(emg_fused_kernel,
                         cudaFuncAttributeMaxDynamicSharedMemorySize,
                         SMEM_FLOATS * (int)sizeof(float));

    emg_fused_kernel<<<B_ * TPB, NTH, SMEM_FLOATS * (int)sizeof(float)>>>(
        X, M, w_env, w_bur, syn, w_dw, w_pw, w_proj, gam, bet, out_h, out_mp);
}